// round 8
// baseline (speedup 1.0000x reference)
#include <cuda_runtime.h>
#include <cuda_bf16.h>

#define NQ 4
#define NL 2
#define NT 256
#define S  4
#define SPB (S * NT)   // samples per block = 1024

typedef unsigned long long ull;

__device__ float d_A[256];  // Re(U^dag Z0 U), 16x16 symmetric

__device__ __forceinline__ ull pack2(float lo, float hi) {
    ull r; asm("mov.b64 %0, {%1, %2};" : "=l"(r) : "f"(lo), "f"(hi)); return r;
}
__device__ __forceinline__ ull dup2(float x) { return pack2(x, x); }
__device__ __forceinline__ void unpack2(ull v, float& lo, float& hi) {
    asm("mov.b64 {%0, %1}, %2;" : "=f"(lo), "=f"(hi) : "l"(v));
}
__device__ __forceinline__ ull ffma2(ull a, ull b, ull c) {
    ull d; asm("fma.rn.f32x2 %0, %1, %2, %3;" : "=l"(d) : "l"(a), "l"(b), "l"(c)); return d;
}
__device__ __forceinline__ ull fmul2(ull a, ull b) {
    ull d; asm("mul.rn.f32x2 %0, %1, %2;" : "=l"(d) : "l"(a), "l"(b)); return d;
}

__device__ __forceinline__ float2 cmul(float2 a, float2 b) {
    return make_float2(a.x * b.x - a.y * b.y, a.x * b.y + a.y * b.x);
}
__device__ __forceinline__ float2 cadd(float2 a, float2 b) {
    return make_float2(a.x + b.x, a.y + b.y);
}

// Build fixed 16x16 circuit unitary from qweights, then A = Re(U^dag Z0 U).
__global__ void qnn_setup_kernel(const float* __restrict__ qw) {
    __shared__ float2 U[16][16];
    int t = threadIdx.x;  // 256 threads
    {
        int r = t >> 4, c = t & 15;
        U[r][c] = make_float2(r == c ? 1.f : 0.f, 0.f);
    }
    __syncthreads();

    for (int l = 0; l < NL; l++) {
        for (int i = 0; i < NQ; i++) {
            float phi = qw[(l * NQ + i) * 3 + 0];
            float th  = qw[(l * NQ + i) * 3 + 1];
            float om  = qw[(l * NQ + i) * 3 + 2];
            float ct = cosf(0.5f * th), st = sinf(0.5f * th);
            float ap = 0.5f * (phi + om), am = 0.5f * (phi - om);
            float cap = cosf(ap), sap = sinf(ap);
            float cam = cosf(am), sam = sinf(am);
            float2 g00 = make_float2( cap * ct, -sap * ct);
            float2 g01 = make_float2(-cam * st, -sam * st);
            float2 g10 = make_float2( cam * st, -sam * st);
            float2 g11 = make_float2( cap * ct,  sap * ct);
            int bit = 3 - i;
            if (t < 128) {
                int pair = t >> 4;
                int c = t & 15;
                int low = pair & ((1 << bit) - 1);
                int hi  = pair >> bit;
                int r0  = (hi << (bit + 1)) | low;
                int r1  = r0 | (1 << bit);
                float2 u0 = U[r0][c], u1 = U[r1][c];
                U[r0][c] = cadd(cmul(g00, u0), cmul(g01, u1));
                U[r1][c] = cadd(cmul(g10, u0), cmul(g11, u1));
            }
            __syncthreads();
        }
        {
            int r = t >> 4, c = t & 15;
            float sign = 1.f;
            if (((r >> 3) & 1) && ((r >> 2) & 1)) sign = -sign;
            if (((r >> 2) & 1) && ((r >> 1) & 1)) sign = -sign;
            if (((r >> 1) & 1) && (r & 1))        sign = -sign;
            U[r][c].x *= sign;
            U[r][c].y *= sign;
        }
        __syncthreads();
    }

    int j = t >> 4, k = t & 15;
    float acc = 0.f;
    #pragma unroll
    for (int r = 0; r < 16; r++) {
        float z = (r & 8) ? -1.f : 1.f;
        acc += z * (U[r][j].x * U[r][k].x + U[r][j].y * U[r][k].y);
    }
    d_A[j * 16 + k] = acc;
}

__global__ __launch_bounds__(NT, 2) void qnn_main_kernel(
    const float* __restrict__ text, const float* __restrict__ image,
    const float* __restrict__ tW1, const float* __restrict__ tb1,
    const float* __restrict__ tW2, const float* __restrict__ tb2,
    const float* __restrict__ iW1, const float* __restrict__ ib1,
    const float* __restrict__ iW2, const float* __restrict__ ib2,
    const float* __restrict__ cW1, const float* __restrict__ cb1,
    const float* __restrict__ cW2, const float* __restrict__ cb2,
    float* __restrict__ out)
{
    __shared__ __align__(16) float s_tW1[16 * 32];
    __shared__ __align__(16) float s_tb1[32];
    __shared__ __align__(16) float s_tW2[32 * 4];
    __shared__ __align__(16) float s_iW1[48 * 64];
    __shared__ __align__(16) float s_ib1[64];
    __shared__ __align__(16) float s_iW2[64 * 4];
    __shared__ __align__(16) float s_A[256];
    __shared__ float s_tb2[4], s_ib2[4];
    __shared__ float s_cW1[16], s_cb1[16], s_cW2[32], s_cb2[2];

    int tid = threadIdx.x;
    for (int i = tid; i < 512; i += NT) s_tW1[i] = tW1[i];
    for (int i = tid; i < 3072; i += NT) s_iW1[i] = iW1[i];
    for (int i = tid; i < 256; i += NT) { s_iW2[i] = iW2[i]; s_A[i] = d_A[i]; }
    for (int i = tid; i < 128; i += NT) s_tW2[i] = tW2[i];
    if (tid < 64) s_ib1[tid] = ib1[tid];
    if (tid < 32) { s_tb1[tid] = tb1[tid]; s_cW2[tid] = cW2[tid]; }
    if (tid < 16) { s_cW1[tid] = cW1[tid]; s_cb1[tid] = cb1[tid]; }
    if (tid < 4) { s_tb2[tid] = tb2[tid]; s_ib2[tid] = ib2[tid]; }
    if (tid < 2) s_cb2[tid] = cb2[tid];
    __syncthreads();

    int base = blockIdx.x * SPB + tid;   // sample s: base + s*NT

    float fb0 = s_tb2[0] + s_ib2[0];
    float fb1 = s_tb2[1] + s_ib2[1];
    float fb2 = s_tb2[2] + s_ib2[2];
    float fb3 = s_tb2[3] + s_ib2[3];
    // feats accumulators, 4 samples x 4 features
    float fa[S][4];
    #pragma unroll
    for (int s = 0; s < S; s++) { fa[s][0] = fb0; fa[s][1] = fb1; fa[s][2] = fb2; fa[s][3] = fb3; }

    // ---- text MLP: 16 -> 32 (relu) -> 4; 4 samples, 2 j-passes of 16 ----
    #pragma unroll
    for (int jt = 0; jt < 2; jt++) {
        ull h[S][8];
        {
            const ulonglong2* bb = (const ulonglong2*)&s_tb1[jt * 16];
            #pragma unroll
            for (int p = 0; p < 4; p++) {
                ulonglong2 v = bb[p];
                #pragma unroll
                for (int s = 0; s < S; s++) { h[s][2*p] = v.x; h[s][2*p+1] = v.y; }
            }
        }
        #pragma unroll
        for (int kb = 0; kb < 4; kb++) {
            float4 v[S];
            #pragma unroll
            for (int s = 0; s < S; s++)
                v[s] = ((const float4*)(text + (size_t)(base + s * NT) * 16))[kb];
            #pragma unroll
            for (int kk = 0; kk < 4; kk++) {
                int k = 4 * kb + kk;
                ull xd[S];
                xd[0] = dup2(kk == 0 ? v[0].x : kk == 1 ? v[0].y : kk == 2 ? v[0].z : v[0].w);
                xd[1] = dup2(kk == 0 ? v[1].x : kk == 1 ? v[1].y : kk == 2 ? v[1].z : v[1].w);
                xd[2] = dup2(kk == 0 ? v[2].x : kk == 1 ? v[2].y : kk == 2 ? v[2].z : v[2].w);
                xd[3] = dup2(kk == 0 ? v[3].x : kk == 1 ? v[3].y : kk == 2 ? v[3].z : v[3].w);
                const ulonglong2* wrow = (const ulonglong2*)&s_tW1[k * 32 + jt * 16];
                #pragma unroll
                for (int p = 0; p < 4; p++) {
                    ulonglong2 w = wrow[p];
                    #pragma unroll
                    for (int s = 0; s < S; s++) {
                        h[s][2*p]   = ffma2(xd[s], w.x, h[s][2*p]);
                        h[s][2*p+1] = ffma2(xd[s], w.y, h[s][2*p+1]);
                    }
                }
            }
        }
        // second layer rows [jt*16, jt*16+16)
        #pragma unroll
        for (int m = 0; m < 8; m++) {
            int r = jt * 16 + 2 * m;
            float4 w0 = *(const float4*)&s_tW2[r * 4];
            float4 w1 = *(const float4*)&s_tW2[(r + 1) * 4];
            #pragma unroll
            for (int s = 0; s < S; s++) {
                float ha, hb;
                unpack2(h[s][m], ha, hb);
                ha = fmaxf(ha, 0.f); hb = fmaxf(hb, 0.f);
                fa[s][0] = fmaf(ha, w0.x, fa[s][0]); fa[s][1] = fmaf(ha, w0.y, fa[s][1]);
                fa[s][2] = fmaf(ha, w0.z, fa[s][2]); fa[s][3] = fmaf(ha, w0.w, fa[s][3]);
                fa[s][0] = fmaf(hb, w1.x, fa[s][0]); fa[s][1] = fmaf(hb, w1.y, fa[s][1]);
                fa[s][2] = fmaf(hb, w1.z, fa[s][2]); fa[s][3] = fmaf(hb, w1.w, fa[s][3]);
            }
        }
    }

    // ---- image MLP: 48 -> 64 (relu) -> 4; 4 samples, 4 j-passes of 16 ----
    #pragma unroll
    for (int jt = 0; jt < 4; jt++) {
        ull h[S][8];
        {
            const ulonglong2* bb = (const ulonglong2*)&s_ib1[jt * 16];
            #pragma unroll
            for (int p = 0; p < 4; p++) {
                ulonglong2 v = bb[p];
                #pragma unroll
                for (int s = 0; s < S; s++) { h[s][2*p] = v.x; h[s][2*p+1] = v.y; }
            }
        }
        #pragma unroll 4
        for (int kb = 0; kb < 12; kb++) {
            float4 v[S];
            #pragma unroll
            for (int s = 0; s < S; s++)
                v[s] = ((const float4*)(image + (size_t)(base + s * NT) * 48))[kb];
            #pragma unroll
            for (int kk = 0; kk < 4; kk++) {
                int k = 4 * kb + kk;
                ull xd[S];
                xd[0] = dup2(kk == 0 ? v[0].x : kk == 1 ? v[0].y : kk == 2 ? v[0].z : v[0].w);
                xd[1] = dup2(kk == 0 ? v[1].x : kk == 1 ? v[1].y : kk == 2 ? v[1].z : v[1].w);
                xd[2] = dup2(kk == 0 ? v[2].x : kk == 1 ? v[2].y : kk == 2 ? v[2].z : v[2].w);
                xd[3] = dup2(kk == 0 ? v[3].x : kk == 1 ? v[3].y : kk == 2 ? v[3].z : v[3].w);
                const ulonglong2* wrow = (const ulonglong2*)&s_iW1[k * 64 + jt * 16];
                #pragma unroll
                for (int p = 0; p < 4; p++) {
                    ulonglong2 w = wrow[p];
                    #pragma unroll
                    for (int s = 0; s < S; s++) {
                        h[s][2*p]   = ffma2(xd[s], w.x, h[s][2*p]);
                        h[s][2*p+1] = ffma2(xd[s], w.y, h[s][2*p+1]);
                    }
                }
            }
        }
        // second layer rows [jt*16, jt*16+16)
        #pragma unroll
        for (int m = 0; m < 8; m++) {
            int r = jt * 16 + 2 * m;
            float4 w0 = *(const float4*)&s_iW2[r * 4];
            float4 w1 = *(const float4*)&s_iW2[(r + 1) * 4];
            #pragma unroll
            for (int s = 0; s < S; s++) {
                float ha, hb;
                unpack2(h[s][m], ha, hb);
                ha = fmaxf(ha, 0.f); hb = fmaxf(hb, 0.f);
                fa[s][0] = fmaf(ha, w0.x, fa[s][0]); fa[s][1] = fmaf(ha, w0.y, fa[s][1]);
                fa[s][2] = fmaf(ha, w0.z, fa[s][2]); fa[s][3] = fmaf(ha, w0.w, fa[s][3]);
                fa[s][0] = fmaf(hb, w1.x, fa[s][0]); fa[s][1] = fmaf(hb, w1.y, fa[s][1]);
                fa[s][2] = fmaf(hb, w1.z, fa[s][2]); fa[s][3] = fmaf(hb, w1.w, fa[s][3]);
            }
        }
    }

    // ---- quantum: half-angle = 0.25*feats_sum; psi outer product ----
    ull psi2[S][8];
    #pragma unroll
    for (int s = 0; s < S; s++) {
        float cc[4], ss[4];
        #pragma unroll
        for (int i = 0; i < 4; i++) __sincosf(0.25f * fa[s][i], &ss[i], &cc[i]);
        float e01[4] = {cc[0]*cc[1], cc[0]*ss[1], ss[0]*cc[1], ss[0]*ss[1]};
        ull e23a = pack2(cc[2]*cc[3], cc[2]*ss[3]);
        ull e23b = pack2(ss[2]*cc[3], ss[2]*ss[3]);
        #pragma unroll
        for (int j = 0; j < 4; j++) {
            ull ed = dup2(e01[j]);
            psi2[s][2*j]   = fmul2(ed, e23a);
            psi2[s][2*j+1] = fmul2(ed, e23b);
        }
    }

    float q[S] = {0.f, 0.f, 0.f, 0.f};
    #pragma unroll
    for (int j = 0; j < 16; j++) {
        const ulonglong2* arow = (const ulonglong2*)&s_A[j * 16];
        ull t[S] = {0ULL, 0ULL, 0ULL, 0ULL};
        #pragma unroll
        for (int p = 0; p < 4; p++) {
            ulonglong2 a2 = arow[p];   // one LDS shared by 4 samples
            #pragma unroll
            for (int s = 0; s < S; s++) {
                t[s] = ffma2(psi2[s][2*p],   a2.x, t[s]);
                t[s] = ffma2(psi2[s][2*p+1], a2.y, t[s]);
            }
        }
        #pragma unroll
        for (int s = 0; s < S; s++) {
            float ta, tb, pj_lo, pj_hi;
            unpack2(t[s], ta, tb);
            unpack2(psi2[s][j >> 1], pj_lo, pj_hi);
            q[s] = fmaf((j & 1) ? pj_hi : pj_lo, ta + tb, q[s]);
        }
    }

    // ---- classifier: q -> 16 (relu) -> 2; shared weight loads ----
    float o0[S], o1[S];
    #pragma unroll
    for (int s = 0; s < S; s++) { o0[s] = s_cb2[0]; o1[s] = s_cb2[1]; }
    #pragma unroll
    for (int m = 0; m < 16; m++) {
        float w = s_cW1[m], bb = s_cb1[m];
        float w20 = s_cW2[2*m], w21 = s_cW2[2*m+1];
        #pragma unroll
        for (int s = 0; s < S; s++) {
            float hh = fmaxf(fmaf(q[s], w, bb), 0.f);
            o0[s] = fmaf(hh, w20, o0[s]);
            o1[s] = fmaf(hh, w21, o1[s]);
        }
    }
    #pragma unroll
    for (int s = 0; s < S; s++)
        ((float2*)out)[base + s * NT] = make_float2(o0[s], o1[s]);
}

extern "C" void kernel_launch(void* const* d_in, const int* in_sizes, int n_in,
                              void* d_out, int out_size) {
    const float* text = (const float*)d_in[0];
    const float* image = (const float*)d_in[1];
    const float* tW1 = (const float*)d_in[2];
    const float* tb1 = (const float*)d_in[3];
    const float* tW2 = (const float*)d_in[4];
    const float* tb2 = (const float*)d_in[5];
    const float* iW1 = (const float*)d_in[6];
    const float* ib1 = (const float*)d_in[7];
    const float* iW2 = (const float*)d_in[8];
    const float* ib2 = (const float*)d_in[9];
    const float* qweights = (const float*)d_in[10];
    const float* cW1 = (const float*)d_in[11];
    const float* cb1 = (const float*)d_in[12];
    const float* cW2 = (const float*)d_in[13];
    const float* cb2 = (const float*)d_in[14];
    float* out = (float*)d_out;

    int B = in_sizes[0] / 16;  // 524288
    qnn_setup_kernel<<<1, 256>>>(qweights);
    qnn_main_kernel<<<B / SPB, NT>>>(text, image, tW1, tb1, tW2, tb2,
                                     iW1, ib1, iW2, ib2,
                                     cW1, cb1, cW2, cb2, out);
}